// round 13
// baseline (speedup 1.0000x reference)
#include <cuda_runtime.h>
#include <cuda_fp16.h>

#define DINL __device__ __forceinline__
typedef unsigned long long ull;
typedef unsigned int uint;
#define FULLM 0xffffffffu

constexpr int V   = 32000;
constexpr int C   = 64;
constexpr int H   = 4;
constexpr int S   = 16;
constexpr int T   = 128;
constexpr int B   = 2;
constexpr int HID = 256;
constexpr int NPE = 4;
constexpr int BT  = B * T;     // 256
constexpr int D4  = 4 * C;     // 256
constexpr int NBLK = 512;      // persistent grid (<= 148 SMs * 4 blocks)

// ---------------- scratch: per-layer rotated buffers (no malloc) --------------
__device__ float   g_pos [NPE * T * C];
__device__ float   g_xb  [NPE + 1][BT * C];
__device__ float   g_xnb [NPE][BT * C];
__device__ float   g_vb  [NPE][H * B * T * S];
__device__ float   g_ob  [NPE][BT * C];
__device__ __half2 g_Qb  [NPE][H * B * T * 128];   // [hb][t][dp]
__device__ __half2 g_Kb  [NPE][H * B * 128 * T];   // [hb][dp][t]

// grid barrier state (zero-init)
__device__ unsigned          g_cnt;
__device__ volatile unsigned g_gen;

DINL float sigmoidf_(float x) { return 1.0f / (1.0f + __expf(-x)); }

DINL ull fma2_(ull a, ull b, ull c) {
    ull r;
    asm("fma.rn.f32x2 %0, %1, %2, %3;" : "=l"(r) : "l"(a), "l"(b), "l"(c));
    return r;
}
DINL ull pack2_(float v) {
    ull r; unsigned u = __float_as_uint(v);
    asm("mov.b64 %0, {%1, %2};" : "=l"(r) : "r"(u), "r"(u));
    return r;
}
DINL ull packlh_(float lo, float hi) {
    ull r;
    asm("mov.b64 %0, {%1, %2};" : "=l"(r) : "r"(__float_as_uint(lo)), "r"(__float_as_uint(hi)));
    return r;
}
DINL void unpack2_(ull v, float& lo, float& hi) {
    unsigned a, b;
    asm("mov.b64 {%0, %1}, %2;" : "=r"(a), "=r"(b) : "l"(v));
    lo = __uint_as_float(a); hi = __uint_as_float(b);
}
DINL float wsum32_(float v) {
#pragma unroll
    for (int off = 16; off; off >>= 1) v += __shfl_xor_sync(FULLM, v, off);
    return v;
}
DINL uint tanh2_(uint x) {
    asm("tanh.approx.f16x2 %0, %1;" : "=r"(x) : "r"(x));
    return x;
}
DINL __half2 u2h_(uint u) { __half2 h; *reinterpret_cast<uint*>(&h) = u; return h; }
DINL uint h2u_(__half2 h) { return *reinterpret_cast<uint*>(&h); }

DINL void gridbar() {
    __threadfence();
    __syncthreads();
    if (threadIdx.x == 0) {
        unsigned gen = g_gen;
        unsigned a = atomicAdd(&g_cnt, 1u);
        if (a == (unsigned)(NBLK - 1)) {
            g_cnt = 0u;
            __threadfence();
            g_gen = gen + 1u;
        } else {
            while (g_gen == gen) { }
        }
        __threadfence();
    }
    __syncthreads();
}

// LayerNorm on a lane-pair (warp-collective), returns normalized pair
DINL void ln_pair(float y0, float y1, const float* g, const float* bta, int lam,
                  float& z0, float& z1) {
    float m = wsum32_(y0 + y1) * (1.f / C);
    float d0 = y0 - m, d1 = y1 - m;
    float var = wsum32_(d0 * d0 + d1 * d1) * (1.f / C);
    float rstd = rsqrtf(var + 1e-5f);
    float2 gv = reinterpret_cast<const float2*>(g)[lam];
    float2 bv = reinterpret_cast<const float2*>(bta)[lam];
    z0 = d0 * rstd * gv.x + bv.x;
    z1 = d1 * rstd * gv.y + bv.y;
}

// ---------------- THE kernel: prologue + 4 layers + lm_head, one launch -------
__global__ void __launch_bounds__(256, 4) k_all(
        const int* __restrict__ idxp, const float* __restrict__ tok,
        const float* __restrict__ tab,
        const float* __restrict__ pW1, const float* __restrict__ pb1,
        const float* __restrict__ pW2, const float* __restrict__ pb2,
        const float* __restrict__ plg, const float* __restrict__ plb,
        const float* __restrict__ g1, const float* __restrict__ b1,
        const float* __restrict__ W1, const float* __restrict__ b1a,
        const float* __restrict__ W2a, const float* __restrict__ valW,
        const float* __restrict__ pW, const float* __restrict__ pb,
        const float* __restrict__ g2, const float* __restrict__ b2,
        const float* __restrict__ fW1, const float* __restrict__ fb1,
        const float* __restrict__ fW2, const float* __restrict__ fb2,
        const float* __restrict__ g3, const float* __restrict__ b3,
        const float* __restrict__ lmW, const float* __restrict__ lmb,
        float* __restrict__ out) {
    int blk = blockIdx.x, tid = threadIdx.x;
    int wid = tid >> 5, lam = tid & 31;
    __shared__ __align__(16) char smraw[8704];

    // ===== PROLOGUE: warp-per-unit. units: 512 pos + 256 embed rows =====
    {
        int gw = blk * 8 + wid;
        if (gw < NPE * T) {
            int p = gw >> 7, t = gw & 127;
            float2 pe2 = reinterpret_cast<const float2*>(tab + (p * T + t) * C)[lam];
            // FFN1 (sigmoid)
            ull a1 = reinterpret_cast<const ull*>(pb1 + p * C)[lam];
            const ull* w1u = reinterpret_cast<const ull*>(pW1 + p * C * C);
#pragma unroll 4
            for (int kp = 0; kp < 32; kp++) {
                float h0 = __shfl_sync(FULLM, pe2.x, kp);
                float h1 = __shfl_sync(FULLM, pe2.y, kp);
                a1 = fma2_(pack2_(h0), w1u[(2 * kp) * 32 + lam], a1);
                a1 = fma2_(pack2_(h1), w1u[(2 * kp + 1) * 32 + lam], a1);
            }
            float s0, s1; unpack2_(a1, s0, s1);
            s0 = sigmoidf_(s0); s1 = sigmoidf_(s1);
            // FFN2
            ull a2 = reinterpret_cast<const ull*>(pb2 + p * C)[lam];
            const ull* w2u = reinterpret_cast<const ull*>(pW2 + p * C * C);
#pragma unroll 4
            for (int kp = 0; kp < 32; kp++) {
                float h0 = __shfl_sync(FULLM, s0, kp);
                float h1 = __shfl_sync(FULLM, s1, kp);
                a2 = fma2_(pack2_(h0), w2u[(2 * kp) * 32 + lam], a2);
                a2 = fma2_(pack2_(h1), w2u[(2 * kp + 1) * 32 + lam], a2);
            }
            float y0, y1; unpack2_(a2, y0, y1);
            float z0, z1;
            ln_pair(y0, y1, plg + p * C, plb + p * C, lam, z0, z1);
            reinterpret_cast<float2*>(g_pos + (p * T + t) * C)[lam] = make_float2(z0, z1);
        } else if (gw < NPE * T + BT) {
            int row = gw - NPE * T;
            int b = row >> 7, t = row & 127;
            float2 x2 = reinterpret_cast<const float2*>(tok + idxp[row] * C)[lam];
            reinterpret_cast<float2*>(g_xb[0] + row * C)[lam] = x2;
            float q0, q1;
            ln_pair(x2.x, x2.y, g1, b1, lam, q0, q1);
            reinterpret_cast<float2*>(g_xnb[0] + row * C)[lam] = make_float2(q0, q1);
            int hv = lam >> 3, sp = lam & 7;
            const ull* vwb = reinterpret_cast<const ull*>(valW) + hv * 512 + sp;
            ull accv = 0ULL;
#pragma unroll 4
            for (int kp = 0; kp < 32; kp++) {
                float k0v = __shfl_sync(FULLM, q0, kp);
                float k1v = __shfl_sync(FULLM, q1, kp);
                accv = fma2_(pack2_(k0v), vwb[kp * 16], accv);
                accv = fma2_(pack2_(k1v), vwb[kp * 16 + 8], accv);
            }
            reinterpret_cast<ull*>(g_vb[0])[((hv * B + b) * T + t) * 8 + sp] = accv;
        }
    }
    gridbar();

#pragma unroll 1
    for (int p = 0; p < NPE; p++) {
        // ===== QK: 128 active blocks, t-tile 8, full d per block =====
        if (blk < 128) {
            int tile = blk & 15, hb = blk >> 4;
            int h = hb >> 1, b = hb & 1;
            int t0 = tile * 8;
            float (*xs)[10] = reinterpret_cast<float(*)[10]>(smraw);
            for (int ix = tid; ix < 128 * 8; ix += 256) {
                int c = ix & 127, tt = ix >> 7;
                xs[c][tt] = (c < 64) ? g_pos[(p * T + t0 + tt) * C + c]
                                     : g_xnb[p][(b * T + t0 + tt) * C + (c - 64)];
            }
            __syncthreads();
            int d = tid;
            ull ak2[4], aq2[4];
            ull bq2 = pack2_(0.5f * b1a[h * D4 + d]);
#pragma unroll
            for (int u = 0; u < 4; u++) { ak2[u] = 0ULL; aq2[u] = bq2; }
            const float* Wk = W1 + h * D4 * D4 + d;
            const float* Wq = Wk + 128 * D4;
            for (int c0 = 0; c0 < 128; c0 += 8) {
                float wk[8], wq[8];
#pragma unroll
                for (int u = 0; u < 8; u++) {
                    wk[u] = Wk[(c0 + u) * D4];
                    wq[u] = Wq[(c0 + u) * D4];
                }
#pragma unroll
                for (int cc = 0; cc < 8; cc++) {
                    ull wk2 = pack2_(0.5f * wk[cc]);
                    ull wq2 = pack2_(0.5f * wq[cc]);
                    const ull* xp = reinterpret_cast<const ull*>(&xs[c0 + cc][0]);
#pragma unroll
                    for (int u = 0; u < 4; u++) {
                        ull xv = xp[u];
                        ak2[u] = fma2_(xv, wk2, ak2[u]);
                        aq2[u] = fma2_(xv, wq2, aq2[u]);
                    }
                }
            }
            int dp = d >> 1;
            bool even = !(d & 1);
#pragma unroll
            for (int u = 0; u < 4; u++) {
                float klo, khi, qlo, qhi;
                unpack2_(ak2[u], klo, khi);
                unpack2_(aq2[u], qlo, qhi);
                float nklo = __shfl_xor_sync(FULLM, klo, 1);
                float nkhi = __shfl_xor_sync(FULLM, khi, 1);
                float nqlo = __shfl_xor_sync(FULLM, qlo, 1);
                float nqhi = __shfl_xor_sync(FULLM, qhi, 1);
                if (even) {
                    g_Kb[p][(size_t)(hb * 128 + dp) * T + t0 + 2 * u]     = __floats2half2_rn(klo, nklo);
                    g_Kb[p][(size_t)(hb * 128 + dp) * T + t0 + 2 * u + 1] = __floats2half2_rn(khi, nkhi);
                    g_Qb[p][(size_t)(hb * T + t0 + 2 * u) * 128 + dp]     = __floats2half2_rn(qlo, nqlo);
                    g_Qb[p][(size_t)(hb * T + t0 + 2 * u + 1) * 128 + dp] = __floats2half2_rn(qhi, nqhi);
                }
            }
        }
        gridbar();

        // ===== ATTN: all 512 blocks, 2 (i,hb) units each (plain L1 loads) =====
        {
            struct At {
                uint qs[128]; uint w2s[128];
                float part[128]; float rb[128]; float wei[128]; float obuf[256];
            };
            At* a = reinterpret_cast<At*>(smraw);
#pragma unroll 1
            for (int u = blk; u < 1024; u += NBLK) {
                int i = u >> 3, hb = u & 7;
                int h = hb >> 1, b = hb & 1;
                __syncthreads();
                if (tid < 128) {
                    a->qs[tid] = reinterpret_cast<const uint*>(
                        g_Qb[p] + (size_t)(hb * T + i) * 128)[tid];
                    a->w2s[tid] = h2u_(__floats2half2_rn(0.5f * W2a[h * D4 + 2 * tid],
                                                         0.5f * W2a[h * D4 + 2 * tid + 1]));
                }
                __syncthreads();
                int j = tid & 127, dh = tid >> 7;
                float acc = 0.f;
                if (j <= i) {
                    const uint* Kc = reinterpret_cast<const uint*>(
                        g_Kb[p] + (size_t)(hb * 128 + dh * 64) * T) + j;
                    const uint* qp = &a->qs[dh * 64];
                    const uint* wp = &a->w2s[dh * 64];
                    for (int dp0 = 0; dp0 < 64; dp0 += 16) {
                        uint kb[16];
#pragma unroll
                        for (int u2 = 0; u2 < 16; u2++) kb[u2] = Kc[(dp0 + u2) * T];
                        uint hacc = 0;
#pragma unroll
                        for (int u2 = 0; u2 < 16; u2++) {
                            uint tv = tanh2_(h2u_(__hadd2(u2h_(qp[dp0 + u2]), u2h_(kb[u2]))));
                            hacc = h2u_(__hfma2(u2h_(wp[dp0 + u2]), u2h_(tv), u2h_(hacc)));
                        }
                        float2 f2 = __half22float2(u2h_(hacc));
                        acc += f2.x + f2.y;
                    }
                }
                if (dh == 1) a->part[j] = acc;
                __syncthreads();
                if (dh == 0) {
                    float sc = (j <= i) ? (acc + a->part[j]) * 0.125f : -1e30f;
                    a->wei[j] = sc;
                    a->rb[j] = sc;
                }
                __syncthreads();
#pragma unroll
                for (int off = 64; off; off >>= 1) {
                    if (tid < off) a->rb[tid] = fmaxf(a->rb[tid], a->rb[tid + off]);
                    __syncthreads();
                }
                float mx = a->rb[0];
                __syncthreads();
                if (dh == 0) a->rb[j] = (j <= i) ? __expf(a->wei[j] - mx) : 0.f;
                __syncthreads();
                if (dh == 0) a->wei[j] = a->rb[j];
#pragma unroll
                for (int off = 64; off; off >>= 1) {
                    if (tid < off) a->rb[tid] += a->rb[tid + off];
                    __syncthreads();
                }
                float inv = __fdividef(1.f, a->rb[0]);
                __syncthreads();
                int part16 = tid >> 4, so = tid & 15;
                const float* vp = g_vb[p] + hb * T * S + so;
                float aa = 0.f;
                for (int jj = part16; jj <= i; jj += 16)
                    aa = fmaf(a->wei[jj], vp[jj * S], aa);
                a->obuf[part16 * 16 + so] = aa;
                __syncthreads();
                if (tid < 16) {
                    float o = 0.f;
#pragma unroll
                    for (int k = 0; k < 16; k++) o += a->obuf[k * 16 + tid];
                    g_ob[p][(b * T + i) * C + h * S + tid] = o * inv;
                }
            }
        }
        gridbar();

        // ===== MLP: 128 active blocks, warp-per-row =====
        if (blk < 128 && wid < 2) {
            ull* hs = reinterpret_cast<ull*>(smraw) + wid * 256;
            int row = blk * 2 + wid;
            int b = row >> 7, t = row & 127;

            float2 o2 = reinterpret_cast<const float2*>(g_ob[p] + row * C)[lam];
            float2 x2 = reinterpret_cast<const float2*>(g_xb[p] + row * C)[lam];
            float2 pb2 = reinterpret_cast<const float2*>(pb)[lam];

            ull acc = packlh_(x2.x + pb2.x, x2.y + pb2.y);
            const ull* pW2 = reinterpret_cast<const ull*>(pW);
#pragma unroll 4
            for (int kp = 0; kp < 32; kp++) {
                float ox = __shfl_sync(FULLM, o2.x, kp);
                float oy = __shfl_sync(FULLM, o2.y, kp);
                acc = fma2_(pack2_(ox), pW2[(2 * kp) * 32 + lam], acc);
                acc = fma2_(pack2_(oy), pW2[(2 * kp + 1) * 32 + lam], acc);
            }
            float xv0, xv1; unpack2_(acc, xv0, xv1);

            float xn0, xn1;
            ln_pair(xv0, xv1, g2, b2, lam, xn0, xn1);

            ull a4[4];
            const ull* fb1u = reinterpret_cast<const ull*>(fb1);
#pragma unroll
            for (int u = 0; u < 4; u++) a4[u] = fb1u[lam * 4 + u];
#pragma unroll 4
            for (int kp = 0; kp < 32; kp++) {
                float k0v = __shfl_sync(FULLM, xn0, kp);
                float k1v = __shfl_sync(FULLM, xn1, kp);
                const ull* r0 = reinterpret_cast<const ull*>(fW1 + (2 * kp) * HID) + lam * 4;
                const ull* r1 = r0 + HID / 2;
                ull p0 = pack2_(k0v), p1 = pack2_(k1v);
#pragma unroll
                for (int u = 0; u < 4; u++) {
                    a4[u] = fma2_(p0, r0[u], a4[u]);
                    a4[u] = fma2_(p1, r1[u], a4[u]);
                }
            }
#pragma unroll
            for (int u = 0; u < 4; u++) {
                float lo, hi; unpack2_(a4[u], lo, hi);
                hs[8 * lam + 2 * u]     = pack2_(sigmoidf_(lo));
                hs[8 * lam + 2 * u + 1] = pack2_(sigmoidf_(hi));
            }
            __syncwarp();

            float2 fb2v = reinterpret_cast<const float2*>(fb2)[lam];
            ull accy = packlh_(xv0 + fb2v.x, xv1 + fb2v.y);
            const ull* fW2u = reinterpret_cast<const ull*>(fW2);
#pragma unroll 8
            for (int k = 0; k < HID; k++)
                accy = fma2_(hs[k], fW2u[k * 32 + lam], accy);
            float y0, y1; unpack2_(accy, y0, y1);

            float z0, z1;
            ln_pair(y0, y1, g3, b3, lam, z0, z1);
            reinterpret_cast<float2*>(g_xb[p + 1] + row * C)[lam] = make_float2(z0, z1);

            if (p < NPE - 1) {
                float q0, q1;
                ln_pair(z0, z1, g1, b1, lam, q0, q1);
                reinterpret_cast<float2*>(g_xnb[p + 1] + row * C)[lam] = make_float2(q0, q1);

                int hv = lam >> 3, sp = lam & 7;
                const ull* vwb = reinterpret_cast<const ull*>(valW) + hv * 512 + sp;
                ull accv = 0ULL;
#pragma unroll 4
                for (int kp = 0; kp < 32; kp++) {
                    float k0v = __shfl_sync(FULLM, q0, kp);
                    float k1v = __shfl_sync(FULLM, q1, kp);
                    accv = fma2_(pack2_(k0v), vwb[kp * 16], accv);
                    accv = fma2_(pack2_(k1v), vwb[kp * 16 + 8], accv);
                }
                reinterpret_cast<ull*>(g_vb[p + 1])[((hv * B + b) * T + t) * 8 + sp] = accv;
            }
        }
        gridbar();
    }

    // ===== LM head: 1000 tiles (125 vocab x 8 row-tiles) over 512 blocks =====
    {
        float (*xs)[68] = reinterpret_cast<float(*)[68]>(smraw);
#pragma unroll 1
        for (int u = blk; u < 1000; u += NBLK) {
            int vt = u % 125, rt = u / 125;
            __syncthreads();
            for (int ix = tid; ix < 32 * 64; ix += 256) {
                int r = ix >> 6, cc = ix & 63;
                xs[r][cc] = g_xb[NPE][(rt * 32 + r) * C + cc];
            }
            __syncthreads();
            int pairi = tid & 127, rh = tid >> 7;
            int vv = vt * 256 + pairi * 2;
            ull bb = *reinterpret_cast<const ull*>(lmb + vv);
            ull acc[16];
#pragma unroll
            for (int r = 0; r < 16; r++) acc[r] = bb;
            for (int cb = 0; cb < 64; cb += 4) {
                const ull w0 = *reinterpret_cast<const ull*>(lmW + (size_t)(cb + 0) * V + vv);
                const ull w1 = *reinterpret_cast<const ull*>(lmW + (size_t)(cb + 1) * V + vv);
                const ull w2 = *reinterpret_cast<const ull*>(lmW + (size_t)(cb + 2) * V + vv);
                const ull w3 = *reinterpret_cast<const ull*>(lmW + (size_t)(cb + 3) * V + vv);
#pragma unroll
                for (int r = 0; r < 16; r++) {
                    const float4 xq = *reinterpret_cast<const float4*>(&xs[rh * 16 + r][cb]);
                    acc[r] = fma2_(w0, pack2_(xq.x), acc[r]);
                    acc[r] = fma2_(w1, pack2_(xq.y), acc[r]);
                    acc[r] = fma2_(w2, pack2_(xq.z), acc[r]);
                    acc[r] = fma2_(w3, pack2_(xq.w), acc[r]);
                }
            }
#pragma unroll
            for (int r = 0; r < 16; r++)
                *reinterpret_cast<ull*>(out + (size_t)(rt * 32 + rh * 16 + r) * V + vv) = acc[r];
        }
    }
}

// ---------------- launch -------------------------------------------------------
extern "C" void kernel_launch(void* const* d_in, const int* in_sizes, int n_in,
                              void* d_out, int out_size) {
    (void)in_sizes; (void)n_in; (void)out_size;
    const int*   idx      = (const int*)  d_in[0];
    const float* tok_emb  = (const float*)d_in[1];
    const float* pe_tab   = (const float*)d_in[2];
    const float* pe_W1    = (const float*)d_in[3];
    const float* pe_b1    = (const float*)d_in[4];
    const float* pe_W2    = (const float*)d_in[5];
    const float* pe_b2    = (const float*)d_in[6];
    const float* pe_lg    = (const float*)d_in[7];
    const float* pe_lb    = (const float*)d_in[8];
    const float* ln1_g    = (const float*)d_in[9];
    const float* ln1_b    = (const float*)d_in[10];
    const float* att_W1   = (const float*)d_in[11];
    const float* att_b1   = (const float*)d_in[12];
    const float* att_W2   = (const float*)d_in[13];
    /* att_b2 = d_in[14] — constant over j, cancels in softmax */
    const float* val_W    = (const float*)d_in[15];
    const float* proj_W   = (const float*)d_in[16];
    const float* proj_b   = (const float*)d_in[17];
    const float* ln2_g    = (const float*)d_in[18];
    const float* ln2_b    = (const float*)d_in[19];
    const float* ff_W1    = (const float*)d_in[20];
    const float* ff_b1    = (const float*)d_in[21];
    const float* ff_W2    = (const float*)d_in[22];
    const float* ff_b2    = (const float*)d_in[23];
    const float* ln3_g    = (const float*)d_in[24];
    const float* ln3_b    = (const float*)d_in[25];
    const float* lm_W     = (const float*)d_in[26];
    const float* lm_b     = (const float*)d_in[27];
    float* out = (float*)d_out;

    k_all<<<NBLK, 256>>>(idx, tok_emb, pe_tab, pe_W1, pe_b1, pe_W2, pe_b2,
                         pe_lg, pe_lb, ln1_g, ln1_b,
                         att_W1, att_b1, att_W2, val_W,
                         proj_W, proj_b, ln2_g, ln2_b,
                         ff_W1, ff_b1, ff_W2, ff_b2, ln3_g, ln3_b,
                         lm_W, lm_b, out);
}

// round 14
// speedup vs baseline: 1.0625x; 1.0625x over previous
#include <cuda_runtime.h>
#include <cuda_fp16.h>

#define DINL __device__ __forceinline__
typedef unsigned long long ull;
typedef unsigned int uint;
#define FULLM 0xffffffffu

constexpr int V   = 32000;
constexpr int C   = 64;
constexpr int H   = 4;
constexpr int S   = 16;
constexpr int T   = 128;
constexpr int B   = 2;
constexpr int HID = 256;
constexpr int NPE = 4;
constexpr int BT  = B * T;     // 256
constexpr int D4  = 4 * C;     // 256

// ---------------- scratch (device globals; no malloc allowed) ----------------
__device__ float   g_x   [BT * C];
__device__ float   g_xn  [BT * C];
__device__ float   g_pos [NPE * T * C];
__device__ __half2 g_Qh2 [H * B * T * 128];   // [hb][t][dp]
__device__ __half2 g_Kh2 [H * B * 128 * T];   // [hb][dp][t]  (coalesced over t)
__device__ float   g_v   [H * B * T * S];     // [hb][t][s]
__device__ float   g_o   [BT * C];

DINL float sigmoidf_(float x) { return 1.0f / (1.0f + __expf(-x)); }

DINL ull fma2_(ull a, ull b, ull c) {
    ull r;
    asm("fma.rn.f32x2 %0, %1, %2, %3;" : "=l"(r) : "l"(a), "l"(b), "l"(c));
    return r;
}
DINL ull pack2_(float v) {
    ull r; unsigned u = __float_as_uint(v);
    asm("mov.b64 %0, {%1, %2};" : "=l"(r) : "r"(u), "r"(u));
    return r;
}
DINL ull packlh_(float lo, float hi) {
    ull r;
    asm("mov.b64 %0, {%1, %2};" : "=l"(r) : "r"(__float_as_uint(lo)), "r"(__float_as_uint(hi)));
    return r;
}
DINL void unpack2_(ull v, float& lo, float& hi) {
    unsigned a, b;
    asm("mov.b64 {%0, %1}, %2;" : "=r"(a), "=r"(b) : "l"(v));
    lo = __uint_as_float(a); hi = __uint_as_float(b);
}
DINL float wsum32_(float v) {
#pragma unroll
    for (int off = 16; off; off >>= 1) v += __shfl_xor_sync(FULLM, v, off);
    return v;
}
DINL uint tanh2_(uint x) {
    asm("tanh.approx.f16x2 %0, %1;" : "=r"(x) : "r"(x));
    return x;
}
DINL __half2 u2h_(uint u) { __half2 h; *reinterpret_cast<uint*>(&h) = u; return h; }
DINL uint h2u_(__half2 h) { return *reinterpret_cast<uint*>(&h); }

// LayerNorm on a lane-pair (warp-collective)
DINL void ln_pair(float y0, float y1, const float* g, const float* bta, int lam,
                  float& z0, float& z1) {
    float m = wsum32_(y0 + y1) * (1.f / C);
    float d0 = y0 - m, d1 = y1 - m;
    float var = wsum32_(d0 * d0 + d1 * d1) * (1.f / C);
    float rstd = rsqrtf(var + 1e-5f);
    float2 gv = reinterpret_cast<const float2*>(g)[lam];
    float2 bv = reinterpret_cast<const float2*>(bta)[lam];
    z0 = d0 * rstd * gv.x + bv.x;
    z1 = d1 * rstd * gv.y + bv.y;
}

// ---------------- K0: prologue — 512 pos units + 256 embed rows, warp-per-unit
__global__ void __launch_bounds__(256) k_prol(
        const int* __restrict__ idxp, const float* __restrict__ tok,
        const float* __restrict__ tab,
        const float* __restrict__ pW1, const float* __restrict__ pb1,
        const float* __restrict__ pW2, const float* __restrict__ pb2,
        const float* __restrict__ plg, const float* __restrict__ plb,
        const float* __restrict__ g1, const float* __restrict__ b1,
        const float* __restrict__ valW) {
    int wid = threadIdx.x >> 5, lam = threadIdx.x & 31;
    int gw = blockIdx.x * 8 + wid;
    if (gw < NPE * T) {
        int p = gw >> 7, t = gw & 127;
        float2 pe2 = reinterpret_cast<const float2*>(tab + (p * T + t) * C)[lam];
        ull a1 = reinterpret_cast<const ull*>(pb1 + p * C)[lam];
        const ull* w1u = reinterpret_cast<const ull*>(pW1 + p * C * C);
#pragma unroll 4
        for (int kp = 0; kp < 32; kp++) {
            float h0 = __shfl_sync(FULLM, pe2.x, kp);
            float h1 = __shfl_sync(FULLM, pe2.y, kp);
            a1 = fma2_(pack2_(h0), w1u[(2 * kp) * 32 + lam], a1);
            a1 = fma2_(pack2_(h1), w1u[(2 * kp + 1) * 32 + lam], a1);
        }
        float s0, s1; unpack2_(a1, s0, s1);
        s0 = sigmoidf_(s0); s1 = sigmoidf_(s1);
        ull a2 = reinterpret_cast<const ull*>(pb2 + p * C)[lam];
        const ull* w2u = reinterpret_cast<const ull*>(pW2 + p * C * C);
#pragma unroll 4
        for (int kp = 0; kp < 32; kp++) {
            float h0 = __shfl_sync(FULLM, s0, kp);
            float h1 = __shfl_sync(FULLM, s1, kp);
            a2 = fma2_(pack2_(h0), w2u[(2 * kp) * 32 + lam], a2);
            a2 = fma2_(pack2_(h1), w2u[(2 * kp + 1) * 32 + lam], a2);
        }
        float y0, y1; unpack2_(a2, y0, y1);
        float z0, z1;
        ln_pair(y0, y1, plg + p * C, plb + p * C, lam, z0, z1);
        reinterpret_cast<float2*>(g_pos + (p * T + t) * C)[lam] = make_float2(z0, z1);
    } else if (gw < NPE * T + BT) {
        int row = gw - NPE * T;
        int b = row >> 7, t = row & 127;
        float2 x2 = reinterpret_cast<const float2*>(tok + idxp[row] * C)[lam];
        reinterpret_cast<float2*>(g_x + row * C)[lam] = x2;
        float q0, q1;
        ln_pair(x2.x, x2.y, g1, b1, lam, q0, q1);
        reinterpret_cast<float2*>(g_xn + row * C)[lam] = make_float2(q0, q1);
        int hv = lam >> 3, sp = lam & 7;
        const ull* vwb = reinterpret_cast<const ull*>(valW) + hv * 512 + sp;
        ull accv = 0ULL;
#pragma unroll 4
        for (int kp = 0; kp < 32; kp++) {
            float k0v = __shfl_sync(FULLM, q0, kp);
            float k1v = __shfl_sync(FULLM, q1, kp);
            accv = fma2_(pack2_(k0v), vwb[kp * 16], accv);
            accv = fma2_(pack2_(k1v), vwb[kp * 16 + 8], accv);
        }
        reinterpret_cast<ull*>(g_v)[((hv * B + b) * T + t) * 8 + sp] = accv;
    }
}

// ---------------- K2: Q/K projections -> half2; Q row-major, K column-major ---
// grid (T/16, H*B, 4 d-quarters), block 64
__global__ void __launch_bounds__(64) k_qk(const float* __restrict__ W1,
                                           const float* __restrict__ b1, int p) {
    int dq = blockIdx.z;
    int hb = blockIdx.y;
    int h = hb >> 1, b = hb & 1;
    int t0 = blockIdx.x * 16;
    int tid = threadIdx.x;              // 0..63
    int d = dq * 64 + tid;

    __shared__ float xs[128][18];

    for (int idx = tid; idx < 128 * 16; idx += 64) {
        int c = idx & 127, tt = idx >> 7;
        xs[c][tt] = (c < 64) ? g_pos[(p * T + t0 + tt) * C + c]
                             : g_xn[(b * T + t0 + tt) * C + (c - 64)];
    }
    __syncthreads();

    ull ak2[8], aq2[8];
    ull bq2 = pack2_(0.5f * b1[h * D4 + d]);
#pragma unroll
    for (int u = 0; u < 8; u++) { ak2[u] = 0ULL; aq2[u] = bq2; }

    const float* Wk = W1 + h * D4 * D4 + d;
    const float* Wq = Wk + 128 * D4;

    for (int c0 = 0; c0 < 128; c0 += 16) {
        float wk[16], wq[16];
#pragma unroll
        for (int u = 0; u < 16; u++) {
            wk[u] = Wk[(c0 + u) * D4];
            wq[u] = Wq[(c0 + u) * D4];
        }
#pragma unroll
        for (int cc = 0; cc < 16; cc++) {
            ull wk2 = pack2_(0.5f * wk[cc]);
            ull wq2 = pack2_(0.5f * wq[cc]);
            const ull* xp = reinterpret_cast<const ull*>(&xs[c0 + cc][0]);
#pragma unroll
            for (int u = 0; u < 8; u++) {
                ull xv = xp[u];
                ak2[u] = fma2_(xv, wk2, ak2[u]);
                aq2[u] = fma2_(xv, wq2, aq2[u]);
            }
        }
    }

    int dp = d >> 1;
    bool even = !(tid & 1);
    __half2* Kb = g_Kh2 + (size_t)(hb * 128 + dp) * T + t0;
#pragma unroll
    for (int u = 0; u < 8; u++) {
        float klo, khi, qlo, qhi;
        unpack2_(ak2[u], klo, khi);
        unpack2_(aq2[u], qlo, qhi);
        float nklo = __shfl_xor_sync(FULLM, klo, 1);
        float nkhi = __shfl_xor_sync(FULLM, khi, 1);
        float nqlo = __shfl_xor_sync(FULLM, qlo, 1);
        float nqhi = __shfl_xor_sync(FULLM, qhi, 1);
        if (even) {
            Kb[2 * u]     = __floats2half2_rn(klo, nklo);
            Kb[2 * u + 1] = __floats2half2_rn(khi, nkhi);
            g_Qh2[(size_t)(hb * T + t0 + 2 * u) * 128 + dp]     = __floats2half2_rn(qlo, nqlo);
            g_Qh2[(size_t)(hb * T + t0 + 2 * u + 1) * 128 + dp] = __floats2half2_rn(qhi, nqhi);
        }
    }
}

// ---------------- K3: per-query attention, f16x2 tanh, coalesced K columns ----
// grid (T, H*B), block 256: tid = dh*128 + j; thread does 64 tanh2.
__global__ void __launch_bounds__(256) k_attn(const float* __restrict__ W2a) {
    int i = blockIdx.x, hb = blockIdx.y;
    int h = hb >> 1, b = hb & 1;
    int tid = threadIdx.x;
    int j = tid & 127, dh = tid >> 7;

    __shared__ uint qs[128], w2s[128];
    __shared__ float part[128];
    __shared__ float rb[128];
    __shared__ float wei[128];
    __shared__ float obuf[256];

    if (tid < 128) {
        qs[tid] = reinterpret_cast<const uint*>(g_Qh2 + (size_t)(hb * T + i) * 128)[tid];
        w2s[tid] = h2u_(__floats2half2_rn(0.5f * W2a[h * D4 + 2 * tid],
                                          0.5f * W2a[h * D4 + 2 * tid + 1]));
    }
    __syncthreads();

    float acc = 0.f;
    if (j <= i) {
        const uint* Kc = reinterpret_cast<const uint*>(
            g_Kh2 + (size_t)(hb * 128 + dh * 64) * T) + j;
        const uint* qp = &qs[dh * 64];
        const uint* wp = &w2s[dh * 64];
        for (int dp0 = 0; dp0 < 64; dp0 += 16) {
            uint kb[16];
#pragma unroll
            for (int u = 0; u < 16; u++) kb[u] = Kc[(dp0 + u) * T];
            uint hacc = 0;
#pragma unroll
            for (int u = 0; u < 16; u++) {
                uint tv = tanh2_(h2u_(__hadd2(u2h_(qp[dp0 + u]), u2h_(kb[u]))));
                hacc = h2u_(__hfma2(u2h_(wp[dp0 + u]), u2h_(tv), u2h_(hacc)));
            }
            float2 f2 = __half22float2(u2h_(hacc));
            acc += f2.x + f2.y;
        }
    }
    if (dh == 1) part[j] = acc;
    __syncthreads();
    if (dh == 0) {
        float sc = (j <= i) ? (acc + part[j]) * 0.125f : -1e30f;
        wei[j] = sc;
        rb[j] = sc;
    }
    __syncthreads();
#pragma unroll
    for (int off = 64; off; off >>= 1) {
        if (tid < off) rb[tid] = fmaxf(rb[tid], rb[tid + off]);
        __syncthreads();
    }
    float mx = rb[0];
    __syncthreads();
    if (dh == 0) rb[j] = (j <= i) ? __expf(wei[j] - mx) : 0.f;
    __syncthreads();
    if (dh == 0) wei[j] = rb[j];
#pragma unroll
    for (int off = 64; off; off >>= 1) {
        if (tid < off) rb[tid] += rb[tid + off];
        __syncthreads();
    }
    float inv = __fdividef(1.f, rb[0]);
    __syncthreads();

    int part16 = tid >> 4, so = tid & 15;
    const float* vp = g_v + hb * T * S + so;
    float a = 0.f;
    for (int jj = part16; jj <= i; jj += 16) a = fmaf(wei[jj], vp[jj * S], a);
    obuf[part16 * 16 + so] = a;
    __syncthreads();
    if (tid < 16) {
        float o = 0.f;
#pragma unroll
        for (int k = 0; k < 16; k++) o += obuf[k * 16 + tid];
        g_o[(b * T + i) * C + h * S + tid] = o * inv;
    }
}

// ---------------- K4: warp-per-row proj+ln2+FFN+ln3, fused ln1+v --------------
__global__ void __launch_bounds__(64) k_mlp(
        const float* __restrict__ pW, const float* __restrict__ pb,
        const float* __restrict__ g2, const float* __restrict__ b2,
        const float* __restrict__ fW1, const float* __restrict__ fb1,
        const float* __restrict__ fW2, const float* __restrict__ fb2,
        const float* __restrict__ g3, const float* __restrict__ b3,
        const float* __restrict__ g1, const float* __restrict__ b1,
        const float* __restrict__ valW, int last) {
    int w = threadIdx.x >> 5, lam = threadIdx.x & 31;
    int row = blockIdx.x * 2 + w;
    int b = row >> 7, t = row & 127;
    __shared__ ull hs2[2][256];

    float2 o2 = reinterpret_cast<const float2*>(g_o)[row * 32 + lam];
    float2 x2 = reinterpret_cast<const float2*>(g_x)[row * 32 + lam];
    float2 pb2 = reinterpret_cast<const float2*>(pb)[lam];

    ull acc = packlh_(x2.x + pb2.x, x2.y + pb2.y);
    const ull* pW2 = reinterpret_cast<const ull*>(pW);
#pragma unroll 4
    for (int kp = 0; kp < 32; kp++) {
        float ox = __shfl_sync(FULLM, o2.x, kp);
        float oy = __shfl_sync(FULLM, o2.y, kp);
        acc = fma2_(pack2_(ox), pW2[(2 * kp) * 32 + lam], acc);
        acc = fma2_(pack2_(oy), pW2[(2 * kp + 1) * 32 + lam], acc);
    }
    float xv0, xv1; unpack2_(acc, xv0, xv1);

    float xn0, xn1;
    ln_pair(xv0, xv1, g2, b2, lam, xn0, xn1);

    ull a4[4];
    const ull* fb1u = reinterpret_cast<const ull*>(fb1);
#pragma unroll
    for (int u = 0; u < 4; u++) a4[u] = fb1u[lam * 4 + u];
#pragma unroll 4
    for (int kp = 0; kp < 32; kp++) {
        float k0v = __shfl_sync(FULLM, xn0, kp);
        float k1v = __shfl_sync(FULLM, xn1, kp);
        const ull* r0 = reinterpret_cast<const ull*>(fW1 + (2 * kp) * HID) + lam * 4;
        const ull* r1 = r0 + HID / 2;
        ull p0 = pack2_(k0v), p1 = pack2_(k1v);
#pragma unroll
        for (int u = 0; u < 4; u++) {
            a4[u] = fma2_(p0, r0[u], a4[u]);
            a4[u] = fma2_(p1, r1[u], a4[u]);
        }
    }
#pragma unroll
    for (int u = 0; u < 4; u++) {
        float lo, hi; unpack2_(a4[u], lo, hi);
        hs2[w][8 * lam + 2 * u]     = pack2_(sigmoidf_(lo));
        hs2[w][8 * lam + 2 * u + 1] = pack2_(sigmoidf_(hi));
    }
    __syncwarp();

    float2 fb2v = reinterpret_cast<const float2*>(fb2)[lam];
    ull accy = packlh_(xv0 + fb2v.x, xv1 + fb2v.y);
    const ull* fW2u = reinterpret_cast<const ull*>(fW2);
#pragma unroll 8
    for (int k = 0; k < HID; k++)
        accy = fma2_(hs2[w][k], fW2u[k * 32 + lam], accy);
    float y0, y1; unpack2_(accy, y0, y1);

    float z0, z1;
    ln_pair(y0, y1, g3, b3, lam, z0, z1);
    reinterpret_cast<float2*>(g_x)[row * 32 + lam] = make_float2(z0, z1);

    if (!last) {
        float q0, q1;
        ln_pair(z0, z1, g1, b1, lam, q0, q1);
        reinterpret_cast<float2*>(g_xn)[row * 32 + lam] = make_float2(q0, q1);

        int hv = lam >> 3, sp = lam & 7;
        const ull* vwb = reinterpret_cast<const ull*>(valW) + hv * 512 + sp;
        ull accv = 0ULL;
#pragma unroll 4
        for (int kp = 0; kp < 32; kp++) {
            float k0v = __shfl_sync(FULLM, q0, kp);
            float k1v = __shfl_sync(FULLM, q1, kp);
            accv = fma2_(pack2_(k0v), vwb[kp * 16], accv);
            accv = fma2_(pack2_(k1v), vwb[kp * 16 + 8], accv);
        }
        reinterpret_cast<ull*>(g_v)[((hv * B + b) * T + t) * 8 + sp] = accv;
    }
}

// ---------------- K5: lm_head, 16 rows x 256 vocab per block, 128 threads -----
__global__ void __launch_bounds__(128) k_lm(const float* __restrict__ W,
                                            const float* __restrict__ bias,
                                            float* __restrict__ out) {
    int vt = blockIdx.x, rt = blockIdx.y;
    int tid = threadIdx.x;
    int rh = tid >> 6;                   // row half: 0 or 1 (8 rows each)
    int vv = vt * 256 + (tid & 63) * 4;  // 4 consecutive vocab
    __shared__ alignas(16) float xs[16][68];
    for (int idx = tid; idx < 16 * 64; idx += 128) {
        int r = idx >> 6, cc = idx & 63;
        xs[r][cc] = g_x[(rt * 16 + r) * C + cc];
    }
    ulonglong2 bb = *reinterpret_cast<const ulonglong2*>(bias + vv);
    ull acc[8][2];
#pragma unroll
    for (int r = 0; r < 8; r++) { acc[r][0] = bb.x; acc[r][1] = bb.y; }
    __syncthreads();
    for (int cb = 0; cb < 64; cb += 4) {
        const ulonglong2 w0 = *reinterpret_cast<const ulonglong2*>(W + (size_t)(cb + 0) * V + vv);
        const ulonglong2 w1 = *reinterpret_cast<const ulonglong2*>(W + (size_t)(cb + 1) * V + vv);
        const ulonglong2 w2 = *reinterpret_cast<const ulonglong2*>(W + (size_t)(cb + 2) * V + vv);
        const ulonglong2 w3 = *reinterpret_cast<const ulonglong2*>(W + (size_t)(cb + 3) * V + vv);
#pragma unroll
        for (int r = 0; r < 8; r++) {
            const float4 xq = *reinterpret_cast<const float4*>(&xs[rh * 8 + r][cb]);
            ull px;
            px = pack2_(xq.x); acc[r][0] = fma2_(w0.x, px, acc[r][0]); acc[r][1] = fma2_(w0.y, px, acc[r][1]);
            px = pack2_(xq.y); acc[r][0] = fma2_(w1.x, px, acc[r][0]); acc[r][1] = fma2_(w1.y, px, acc[r][1]);
            px = pack2_(xq.z); acc[r][0] = fma2_(w2.x, px, acc[r][0]); acc[r][1] = fma2_(w2.y, px, acc[r][1]);
            px = pack2_(xq.w); acc[r][0] = fma2_(w3.x, px, acc[r][0]); acc[r][1] = fma2_(w3.y, px, acc[r][1]);
        }
    }
#pragma unroll
    for (int r = 0; r < 8; r++) {
        ulonglong2 o2; o2.x = acc[r][0]; o2.y = acc[r][1];
        *reinterpret_cast<ulonglong2*>(out + (size_t)(rt * 16 + rh * 8 + r) * V + vv) = o2;
    }
}

// ---------------- launch -------------------------------------------------------
extern "C" void kernel_launch(void* const* d_in, const int* in_sizes, int n_in,
                              void* d_out, int out_size) {
    (void)in_sizes; (void)n_in; (void)out_size;
    const int*   idx      = (const int*)  d_in[0];
    const float* tok_emb  = (const float*)d_in[1];
    const float* pe_tab   = (const float*)d_in[2];
    const float* pe_W1    = (const float*)d_in[3];
    const float* pe_b1    = (const float*)d_in[4];
    const float* pe_W2    = (const float*)d_in[5];
    const float* pe_b2    = (const float*)d_in[6];
    const float* pe_lg    = (const float*)d_in[7];
    const float* pe_lb    = (const float*)d_in[8];
    const float* ln1_g    = (const float*)d_in[9];
    const float* ln1_b    = (const float*)d_in[10];
    const float* att_W1   = (const float*)d_in[11];
    const float* att_b1   = (const float*)d_in[12];
    const float* att_W2   = (const float*)d_in[13];
    /* att_b2 = d_in[14] — constant over j, cancels in softmax */
    const float* val_W    = (const float*)d_in[15];
    const float* proj_W   = (const float*)d_in[16];
    const float* proj_b   = (const float*)d_in[17];
    const float* ln2_g    = (const float*)d_in[18];
    const float* ln2_b    = (const float*)d_in[19];
    const float* ff_W1    = (const float*)d_in[20];
    const float* ff_b1    = (const float*)d_in[21];
    const float* ff_W2    = (const float*)d_in[22];
    const float* ff_b2    = (const float*)d_in[23];
    const float* ln3_g    = (const float*)d_in[24];
    const float* ln3_b    = (const float*)d_in[25];
    const float* lm_W     = (const float*)d_in[26];
    const float* lm_b     = (const float*)d_in[27];
    float* out = (float*)d_out;

    k_prol<<<96, 256>>>(idx, tok_emb, pe_tab, pe_W1, pe_b1, pe_W2, pe_b2,
                        pe_lg, pe_lb, ln1_g, ln1_b, val_W);
    for (int p = 0; p < NPE; p++) {
        k_qk  <<<dim3(T / 16, H * B, 4), 64>>>(att_W1, att_b1, p);
        k_attn<<<dim3(T, H * B), 256>>>(att_W2);
        k_mlp <<<BT / 2, 64>>>(proj_W, proj_b, ln2_g, ln2_b,
                               ff_W1, ff_b1, ff_W2, ff_b2, ln3_g, ln3_b,
                               ln1_g, ln1_b, val_W, p == NPE - 1);
    }
    k_lm<<<dim3(V / 256, BT / 16), 128>>>(lm_W, lm_b, out);
}

// round 15
// speedup vs baseline: 1.2796x; 1.2043x over previous
#include <cuda_runtime.h>
#include <cuda_fp16.h>

#define DINL __device__ __forceinline__
typedef unsigned long long ull;
typedef unsigned int uint;
#define FULLM 0xffffffffu

constexpr int V   = 32000;
constexpr int C   = 64;
constexpr int H   = 4;
constexpr int S   = 16;
constexpr int T   = 128;
constexpr int B   = 2;
constexpr int HID = 256;
constexpr int NPE = 4;
constexpr int BT  = B * T;     // 256
constexpr int D4  = 4 * C;     // 256

// ---------------- scratch (device globals; no malloc allowed) ----------------
__device__ float   g_x   [BT * C];
__device__ float   g_xn  [BT * C];
__device__ float   g_pos [NPE * T * C];
__device__ __half2 g_Qh2 [H * B * T * 128];   // [hb][t][dp]
__device__ __half2 g_Kh2 [H * B * 128 * T];   // [hb][dp][t]  (coalesced over t)
__device__ float   g_v   [H * B * T * S];     // [hb][t][s]
__device__ float   g_o   [BT * C];

DINL float sigmoidf_(float x) { return 1.0f / (1.0f + __expf(-x)); }

DINL ull fma2_(ull a, ull b, ull c) {
    ull r;
    asm("fma.rn.f32x2 %0, %1, %2, %3;" : "=l"(r) : "l"(a), "l"(b), "l"(c));
    return r;
}
DINL ull pack2_(float v) {
    ull r; unsigned u = __float_as_uint(v);
    asm("mov.b64 %0, {%1, %2};" : "=l"(r) : "r"(u), "r"(u));
    return r;
}
DINL ull packlh_(float lo, float hi) {
    ull r;
    asm("mov.b64 %0, {%1, %2};" : "=l"(r) : "r"(__float_as_uint(lo)), "r"(__float_as_uint(hi)));
    return r;
}
DINL void unpack2_(ull v, float& lo, float& hi) {
    unsigned a, b;
    asm("mov.b64 {%0, %1}, %2;" : "=r"(a), "=r"(b) : "l"(v));
    lo = __uint_as_float(a); hi = __uint_as_float(b);
}
DINL ull add2_(ull a, ull b) {
    ull r;
    asm("add.rn.f32x2 %0, %1, %2;" : "=l"(r) : "l"(a), "l"(b));
    return r;
}
DINL uint tanh2_(uint x) {
    asm("tanh.approx.f16x2 %0, %1;" : "=r"(x) : "r"(x));
    return x;
}
DINL __half2 u2h_(uint u) { __half2 h; *reinterpret_cast<uint*>(&h) = u; return h; }
DINL uint h2u_(__half2 h) { return *reinterpret_cast<uint*>(&h); }

// LayerNorm on a lane-pair: E[x]/E[x^2] reduced in interleaved (concurrent) chains
DINL void ln_pair(float y0, float y1, const float* g, const float* bta, int lam,
                  float& z0, float& z1) {
    float s = y0 + y1;
    float q = y0 * y0 + y1 * y1;
#pragma unroll
    for (int off = 16; off; off >>= 1) {
        s += __shfl_xor_sync(FULLM, s, off);
        q += __shfl_xor_sync(FULLM, q, off);
    }
    float m = s * (1.f / C);
    float var = fmaxf(q * (1.f / C) - m * m, 0.f);
    float rstd = rsqrtf(var + 1e-5f);
    float2 gv = reinterpret_cast<const float2*>(g)[lam];
    float2 bv = reinterpret_cast<const float2*>(bta)[lam];
    z0 = (y0 - m) * rstd * gv.x + bv.x;
    z1 = (y1 - m) * rstd * gv.y + bv.y;
}

// ---------------- K0: prologue — 512 pos units + 256 embed rows, warp-per-unit
__global__ void __launch_bounds__(256) k_prol(
        const int* __restrict__ idxp, const float* __restrict__ tok,
        const float* __restrict__ tab,
        const float* __restrict__ pW1, const float* __restrict__ pb1,
        const float* __restrict__ pW2, const float* __restrict__ pb2,
        const float* __restrict__ plg, const float* __restrict__ plb,
        const float* __restrict__ g1, const float* __restrict__ b1,
        const float* __restrict__ valW) {
    int wid = threadIdx.x >> 5, lam = threadIdx.x & 31;
    int gw = blockIdx.x * 8 + wid;
    if (gw < NPE * T) {
        int p = gw >> 7, t = gw & 127;
        float2 pe2 = reinterpret_cast<const float2*>(tab + (p * T + t) * C)[lam];
        ull a1 = reinterpret_cast<const ull*>(pb1 + p * C)[lam];
        const ull* w1u = reinterpret_cast<const ull*>(pW1 + p * C * C);
#pragma unroll 4
        for (int kp = 0; kp < 32; kp++) {
            float h0 = __shfl_sync(FULLM, pe2.x, kp);
            float h1 = __shfl_sync(FULLM, pe2.y, kp);
            a1 = fma2_(pack2_(h0), w1u[(2 * kp) * 32 + lam], a1);
            a1 = fma2_(pack2_(h1), w1u[(2 * kp + 1) * 32 + lam], a1);
        }
        float s0, s1; unpack2_(a1, s0, s1);
        s0 = sigmoidf_(s0); s1 = sigmoidf_(s1);
        ull a2 = reinterpret_cast<const ull*>(pb2 + p * C)[lam];
        const ull* w2u = reinterpret_cast<const ull*>(pW2 + p * C * C);
#pragma unroll 4
        for (int kp = 0; kp < 32; kp++) {
            float h0 = __shfl_sync(FULLM, s0, kp);
            float h1 = __shfl_sync(FULLM, s1, kp);
            a2 = fma2_(pack2_(h0), w2u[(2 * kp) * 32 + lam], a2);
            a2 = fma2_(pack2_(h1), w2u[(2 * kp + 1) * 32 + lam], a2);
        }
        float y0, y1; unpack2_(a2, y0, y1);
        float z0, z1;
        ln_pair(y0, y1, plg + p * C, plb + p * C, lam, z0, z1);
        reinterpret_cast<float2*>(g_pos + (p * T + t) * C)[lam] = make_float2(z0, z1);
    } else if (gw < NPE * T + BT) {
        int row = gw - NPE * T;
        int b = row >> 7, t = row & 127;
        float2 x2 = reinterpret_cast<const float2*>(tok + idxp[row] * C)[lam];
        reinterpret_cast<float2*>(g_x + row * C)[lam] = x2;
        float q0, q1;
        ln_pair(x2.x, x2.y, g1, b1, lam, q0, q1);
        reinterpret_cast<float2*>(g_xn + row * C)[lam] = make_float2(q0, q1);
        int hv = lam >> 3, sp = lam & 7;
        const ull* vwb = reinterpret_cast<const ull*>(valW) + hv * 512 + sp;
        ull accv = 0ULL;
#pragma unroll 4
        for (int kp = 0; kp < 32; kp++) {
            float k0v = __shfl_sync(FULLM, q0, kp);
            float k1v = __shfl_sync(FULLM, q1, kp);
            accv = fma2_(pack2_(k0v), vwb[kp * 16], accv);
            accv = fma2_(pack2_(k1v), vwb[kp * 16 + 8], accv);
        }
        reinterpret_cast<ull*>(g_v)[((hv * B + b) * T + t) * 8 + sp] = accv;
    }
}

// ---------------- K2: Q/K projections -> half2; Q row-major, K column-major ---
// grid (T/16, H*B, 4 d-quarters), block 64
__global__ void __launch_bounds__(64) k_qk(const float* __restrict__ W1,
                                           const float* __restrict__ b1, int p) {
    int dq = blockIdx.z;
    int hb = blockIdx.y;
    int h = hb >> 1, b = hb & 1;
    int t0 = blockIdx.x * 16;
    int tid = threadIdx.x;              // 0..63
    int d = dq * 64 + tid;

    __shared__ float xs[128][18];

    for (int idx = tid; idx < 128 * 16; idx += 64) {
        int c = idx & 127, tt = idx >> 7;
        xs[c][tt] = (c < 64) ? g_pos[(p * T + t0 + tt) * C + c]
                             : g_xn[(b * T + t0 + tt) * C + (c - 64)];
    }
    __syncthreads();

    ull ak2[8], aq2[8];
    ull bq2 = pack2_(0.5f * b1[h * D4 + d]);
#pragma unroll
    for (int u = 0; u < 8; u++) { ak2[u] = 0ULL; aq2[u] = bq2; }

    const float* Wk = W1 + h * D4 * D4 + d;
    const float* Wq = Wk + 128 * D4;

    for (int c0 = 0; c0 < 128; c0 += 16) {
        float wk[16], wq[16];
#pragma unroll
        for (int u = 0; u < 16; u++) {
            wk[u] = Wk[(c0 + u) * D4];
            wq[u] = Wq[(c0 + u) * D4];
        }
#pragma unroll
        for (int cc = 0; cc < 16; cc++) {
            ull wk2 = pack2_(0.5f * wk[cc]);
            ull wq2 = pack2_(0.5f * wq[cc]);
            const ull* xp = reinterpret_cast<const ull*>(&xs[c0 + cc][0]);
#pragma unroll
            for (int u = 0; u < 8; u++) {
                ull xv = xp[u];
                ak2[u] = fma2_(xv, wk2, ak2[u]);
                aq2[u] = fma2_(xv, wq2, aq2[u]);
            }
        }
    }

    int dp = d >> 1;
    bool even = !(tid & 1);
    __half2* Kb = g_Kh2 + (size_t)(hb * 128 + dp) * T + t0;
#pragma unroll
    for (int u = 0; u < 8; u++) {
        float klo, khi, qlo, qhi;
        unpack2_(ak2[u], klo, khi);
        unpack2_(aq2[u], qlo, qhi);
        float nklo = __shfl_xor_sync(FULLM, klo, 1);
        float nkhi = __shfl_xor_sync(FULLM, khi, 1);
        float nqlo = __shfl_xor_sync(FULLM, qlo, 1);
        float nqhi = __shfl_xor_sync(FULLM, qhi, 1);
        if (even) {
            Kb[2 * u]     = __floats2half2_rn(klo, nklo);
            Kb[2 * u + 1] = __floats2half2_rn(khi, nkhi);
            g_Qh2[(size_t)(hb * T + t0 + 2 * u) * 128 + dp]     = __floats2half2_rn(qlo, nqlo);
            g_Qh2[(size_t)(hb * T + t0 + 2 * u + 1) * 128 + dp] = __floats2half2_rn(qhi, nqhi);
        }
    }
}

// ---------------- K3: per-query attention, f16x2 tanh, coalesced K columns ----
// grid (T, H*B), block 256: tid = dh*128 + j; thread does 64 tanh2.
__global__ void __launch_bounds__(256) k_attn(const float* __restrict__ W2a) {
    int i = blockIdx.x, hb = blockIdx.y;
    int h = hb >> 1, b = hb & 1;
    int tid = threadIdx.x;
    int j = tid & 127, dh = tid >> 7;

    __shared__ uint qs[128], w2s[128];
    __shared__ float part[128];
    __shared__ float rb[128];
    __shared__ float wei[128];
    __shared__ float obuf[256];

    if (tid < 128) {
        qs[tid] = reinterpret_cast<const uint*>(g_Qh2 + (size_t)(hb * T + i) * 128)[tid];
        w2s[tid] = h2u_(__floats2half2_rn(0.5f * W2a[h * D4 + 2 * tid],
                                          0.5f * W2a[h * D4 + 2 * tid + 1]));
    }
    __syncthreads();

    float acc = 0.f;
    if (j <= i) {
        const uint* Kc = reinterpret_cast<const uint*>(
            g_Kh2 + (size_t)(hb * 128 + dh * 64) * T) + j;
        const uint* qp = &qs[dh * 64];
        const uint* wp = &w2s[dh * 64];
        for (int dp0 = 0; dp0 < 64; dp0 += 16) {
            uint kb[16];
#pragma unroll
            for (int u = 0; u < 16; u++) kb[u] = Kc[(dp0 + u) * T];
            uint hacc = 0;
#pragma unroll
            for (int u = 0; u < 16; u++) {
                uint tv = tanh2_(h2u_(__hadd2(u2h_(qp[dp0 + u]), u2h_(kb[u]))));
                hacc = h2u_(__hfma2(u2h_(wp[dp0 + u]), u2h_(tv), u2h_(hacc)));
            }
            float2 f2 = __half22float2(u2h_(hacc));
            acc += f2.x + f2.y;
        }
    }
    if (dh == 1) part[j] = acc;
    __syncthreads();
    if (dh == 0) {
        float sc = (j <= i) ? (acc + part[j]) * 0.125f : -1e30f;
        wei[j] = sc;
        rb[j] = sc;
    }
    __syncthreads();
#pragma unroll
    for (int off = 64; off; off >>= 1) {
        if (tid < off) rb[tid] = fmaxf(rb[tid], rb[tid + off]);
        __syncthreads();
    }
    float mx = rb[0];
    __syncthreads();
    if (dh == 0) rb[j] = (j <= i) ? __expf(wei[j] - mx) : 0.f;
    __syncthreads();
    if (dh == 0) wei[j] = rb[j];
#pragma unroll
    for (int off = 64; off; off >>= 1) {
        if (tid < off) rb[tid] += rb[tid + off];
        __syncthreads();
    }
    float inv = __fdividef(1.f, rb[0]);
    __syncthreads();

    int part16 = tid >> 4, so = tid & 15;
    const float* vp = g_v + hb * T * S + so;
    float a = 0.f;
    for (int jj = part16; jj <= i; jj += 16) a = fmaf(wei[jj], vp[jj * S], a);
    obuf[part16 * 16 + so] = a;
    __syncthreads();
    if (tid < 16) {
        float o = 0.f;
#pragma unroll
        for (int k = 0; k < 16; k++) o += obuf[k * 16 + tid];
        g_o[(b * T + i) * C + h * S + tid] = o * inv;
    }
}

// ---------------- K4: warp-per-row MLP, deep-ILP accumulators -----------------
// grid BT blocks x 32 threads (one warp per row)
__global__ void __launch_bounds__(32) k_mlp(
        const float* __restrict__ pW, const float* __restrict__ pb,
        const float* __restrict__ g2, const float* __restrict__ b2,
        const float* __restrict__ fW1, const float* __restrict__ fb1,
        const float* __restrict__ fW2, const float* __restrict__ fb2,
        const float* __restrict__ g3, const float* __restrict__ b3,
        const float* __restrict__ g1, const float* __restrict__ b1,
        const float* __restrict__ valW, int last) {
    int lam = threadIdx.x;
    int row = blockIdx.x;
    int b = row >> 7, t = row & 127;
    __shared__ ull hs[256];

    float2 o2 = reinterpret_cast<const float2*>(g_o)[row * 32 + lam];
    float2 x2 = reinterpret_cast<const float2*>(g_x)[row * 32 + lam];
    float2 pb2 = reinterpret_cast<const float2*>(pb)[lam];

    // proj + residual: two independent 32-deep chains
    ull accA = packlh_(x2.x + pb2.x, x2.y + pb2.y);
    ull accB = 0ULL;
    const ull* pW2 = reinterpret_cast<const ull*>(pW);
#pragma unroll 4
    for (int kp = 0; kp < 32; kp++) {
        float ox = __shfl_sync(FULLM, o2.x, kp);
        float oy = __shfl_sync(FULLM, o2.y, kp);
        accA = fma2_(pack2_(ox), pW2[(2 * kp) * 32 + lam], accA);
        accB = fma2_(pack2_(oy), pW2[(2 * kp + 1) * 32 + lam], accB);
    }
    ull acc = add2_(accA, accB);
    float xv0, xv1; unpack2_(acc, xv0, xv1);

    float xn0, xn1;
    ln_pair(xv0, xv1, g2, b2, lam, xn0, xn1);

    // FFN1: 8 independent 32-deep chains (lane owns hid [8lam, 8lam+8))
    ull a4e[4], a4o[4];
    const ull* fb1u = reinterpret_cast<const ull*>(fb1);
#pragma unroll
    for (int u = 0; u < 4; u++) { a4e[u] = fb1u[lam * 4 + u]; a4o[u] = 0ULL; }
#pragma unroll 4
    for (int kp = 0; kp < 32; kp++) {
        float k0v = __shfl_sync(FULLM, xn0, kp);
        float k1v = __shfl_sync(FULLM, xn1, kp);
        const ull* r0 = reinterpret_cast<const ull*>(fW1 + (2 * kp) * HID) + lam * 4;
        const ull* r1 = r0 + HID / 2;
        ull p0 = pack2_(k0v), p1 = pack2_(k1v);
#pragma unroll
        for (int u = 0; u < 4; u++) {
            a4e[u] = fma2_(p0, r0[u], a4e[u]);
            a4o[u] = fma2_(p1, r1[u], a4o[u]);
        }
    }
#pragma unroll
    for (int u = 0; u < 4; u++) {
        float lo, hi; unpack2_(add2_(a4e[u], a4o[u]), lo, hi);
        hs[8 * lam + 2 * u]     = pack2_(sigmoidf_(lo));
        hs[8 * lam + 2 * u + 1] = pack2_(sigmoidf_(hi));
    }
    __syncwarp();

    // FFN2 + residual: 4 independent 64-deep chains
    float2 fb2v = reinterpret_cast<const float2*>(fb2)[lam];
    ull ay0 = packlh_(xv0 + fb2v.x, xv1 + fb2v.y);
    ull ay1 = 0ULL, ay2 = 0ULL, ay3 = 0ULL;
    const ull* fW2u = reinterpret_cast<const ull*>(fW2);
#pragma unroll 8
    for (int k = 0; k < HID; k += 4) {
        ay0 = fma2_(hs[k],     fW2u[(k)     * 32 + lam], ay0);
        ay1 = fma2_(hs[k + 1], fW2u[(k + 1) * 32 + lam], ay1);
        ay2 = fma2_(hs[k + 2], fW2u[(k + 2) * 32 + lam], ay2);
        ay3 = fma2_(hs[k + 3], fW2u[(k + 3) * 32 + lam], ay3);
    }
    ull accy = add2_(add2_(ay0, ay1), add2_(ay2, ay3));
    float y0, y1; unpack2_(accy, y0, y1);

    float z0, z1;
    ln_pair(y0, y1, g3, b3, lam, z0, z1);
    reinterpret_cast<float2*>(g_x)[row * 32 + lam] = make_float2(z0, z1);

    if (!last) {
        float q0, q1;
        ln_pair(z0, z1, g1, b1, lam, q0, q1);
        reinterpret_cast<float2*>(g_xn)[row * 32 + lam] = make_float2(q0, q1);

        int hv = lam >> 3, sp = lam & 7;
        const ull* vwb = reinterpret_cast<const ull*>(valW) + hv * 512 + sp;
        ull avA = 0ULL, avB = 0ULL;
#pragma unroll 4
        for (int kp = 0; kp < 32; kp++) {
            float k0v = __shfl_sync(FULLM, q0, kp);
            float k1v = __shfl_sync(FULLM, q1, kp);
            avA = fma2_(pack2_(k0v), vwb[kp * 16], avA);
            avB = fma2_(pack2_(k1v), vwb[kp * 16 + 8], avB);
        }
        reinterpret_cast<ull*>(g_v)[((hv * B + b) * T + t) * 8 + sp] = add2_(avA, avB);
    }
}

// ---------------- K5: lm_head, 16 rows x 256 vocab per block, 128 threads -----
__global__ void __launch_bounds__(128) k_lm(const float* __restrict__ W,
                                            const float* __restrict__ bias,
                                            float* __restrict__ out) {
    int vt = blockIdx.x, rt = blockIdx.y;
    int tid = threadIdx.x;
    int rh = tid >> 6;                   // row half: 0 or 1 (8 rows each)
    int vv = vt * 256 + (tid & 63) * 4;  // 4 consecutive vocab
    __shared__ alignas(16) float xs[16][68];
    for (int idx = tid; idx < 16 * 64; idx += 128) {
        int r = idx >> 6, cc = idx & 63;
        xs[r][cc] = g_x[(rt * 16 + r) * C + cc];
    }
    ulonglong2 bb = *reinterpret_cast<const ulonglong2*>(bias + vv);
    ull acc[8][2];
#pragma unroll
    for (int r = 0; r < 8; r++) { acc[r][0] = bb.x; acc[r][1] = bb.y; }
    __syncthreads();
    for (int cb = 0; cb < 64; cb += 4) {
        const ulonglong2 w0 = *reinterpret_cast<const ulonglong2*>(W + (size_t)(cb + 0) * V + vv);
        const ulonglong2 w1 = *reinterpret_cast<const ulonglong2*>(W + (size_t)(cb + 1) * V + vv);
        const ulonglong2 w2 = *reinterpret_cast<const ulonglong2*>(W + (size_t)(cb + 2) * V + vv);
        const ulonglong2 w3 = *reinterpret_cast<const ulonglong2*>(W + (size_t)(cb + 3) * V + vv);
#pragma unroll
        for (int r = 0; r < 8; r++) {
            const float4 xq = *reinterpret_cast<const float4*>(&xs[rh * 8 + r][cb]);
            ull px;
            px = pack2_(xq.x); acc[r][0] = fma2_(w0.x, px, acc[r][0]); acc[r][1] = fma2_(w0.y, px, acc[r][1]);
            px = pack2_(xq.y); acc[r][0] = fma2_(w1.x, px, acc[r][0]); acc[r][1] = fma2_(w1.y, px, acc[r][1]);
            px = pack2_(xq.z); acc[r][0] = fma2_(w2.x, px, acc[r][0]); acc[r][1] = fma2_(w2.y, px, acc[r][1]);
            px = pack2_(xq.w); acc[r][0] = fma2_(w3.x, px, acc[r][0]); acc[r][1] = fma2_(w3.y, px, acc[r][1]);
        }
    }
#pragma unroll
    for (int r = 0; r < 8; r++) {
        ulonglong2 o2; o2.x = acc[r][0]; o2.y = acc[r][1];
        *reinterpret_cast<ulonglong2*>(out + (size_t)(rt * 16 + rh * 8 + r) * V + vv) = o2;
    }
}

// ---------------- launch -------------------------------------------------------
extern "C" void kernel_launch(void* const* d_in, const int* in_sizes, int n_in,
                              void* d_out, int out_size) {
    (void)in_sizes; (void)n_in; (void)out_size;
    const int*   idx      = (const int*)  d_in[0];
    const float* tok_emb  = (const float*)d_in[1];
    const float* pe_tab   = (const float*)d_in[2];
    const float* pe_W1    = (const float*)d_in[3];
    const float* pe_b1    = (const float*)d_in[4];
    const float* pe_W2    = (const float*)d_in[5];
    const float* pe_b2    = (const float*)d_in[6];
    const float* pe_lg    = (const float*)d_in[7];
    const float* pe_lb    = (const float*)d_in[8];
    const float* ln1_g    = (const float*)d_in[9];
    const float* ln1_b    = (const float*)d_in[10];
    const float* att_W1   = (const float*)d_in[11];
    const float* att_b1   = (const float*)d_in[12];
    const float* att_W2   = (const float*)d_in[13];
    /* att_b2 = d_in[14] — constant over j, cancels in softmax */
    const float* val_W    = (const float*)d_in[15];
    const float* proj_W   = (const float*)d_in[16];
    const float* proj_b   = (const float*)d_in[17];
    const float* ln2_g    = (const float*)d_in[18];
    const float* ln2_b    = (const float*)d_in[19];
    const float* ff_W1    = (const float*)d_in[20];
    const float* ff_b1    = (const float*)d_in[21];
    const float* ff_W2    = (const float*)d_in[22];
    const float* ff_b2    = (const float*)d_in[23];
    const float* ln3_g    = (const float*)d_in[24];
    const float* ln3_b    = (const float*)d_in[25];
    const float* lm_W     = (const float*)d_in[26];
    const float* lm_b     = (const float*)d_in[27];
    float* out = (float*)d_out;

    k_prol<<<96, 256>>>(idx, tok_emb, pe_tab, pe_W1, pe_b1, pe_W2, pe_b2,
                        pe_lg, pe_lb, ln1_g, ln1_b, val_W);
    for (int p = 0; p < NPE; p++) {
        k_qk  <<<dim3(T / 16, H * B, 4), 64>>>(att_W1, att_b1, p);
        k_attn<<<dim3(T, H * B), 256>>>(att_W2);
        k_mlp <<<BT, 32>>>(proj_W, proj_b, ln2_g, ln2_b,
                           ff_W1, ff_b1, ff_W2, ff_b2, ln3_g, ln3_b,
                           ln1_g, ln1_b, val_W, p == NPE - 1);
    }
    k_lm<<<dim3(V / 256, BT / 16), 128>>>(lm_W, lm_b, out);
}